// round 16
// baseline (speedup 1.0000x reference)
#include <cuda_runtime.h>
#include <cstdint>

// Problem constants
#define NB 2
#define NS 256
#define ND 256
#define NH 1024
#define NE 16
#define NK 2

constexpr int NT = NB * NS;      // 512 tokens
constexpr int NP = NT * NK;      // 1024 (token, k) pairs

// Scratch (device globals: allocation-free per harness rules)
__device__ int g_counts[NE];
__device__ int g_pairs[NE * NP];

__device__ __forceinline__ float gelu_tanh(float v) {
    const float c = 0.7978845608028654f;  // sqrt(2/pi)
    float u = c * (v + 0.044715f * v * v * v);
    return 0.5f * v * (1.0f + tanhf(u));
}

// fp32 -> tf32 bits, round-to-nearest
__device__ __forceinline__ uint32_t to_tf32(float f) {
    uint32_t r;
    asm("cvt.rna.tf32.f32 %0, %1;" : "=r"(r) : "f"(f));
    return r;
}
__device__ __forceinline__ uint4 to_tf32x4(float4 v) {
    uint4 r;
    r.x = to_tf32(v.x); r.y = to_tf32(v.y); r.z = to_tf32(v.z); r.w = to_tf32(v.w);
    return r;
}

// D(16x8) += A(16x8,row) * B(8x8,col), tf32 inputs, f32 accum.
__device__ __forceinline__ void mma_tf32(float* c, const uint32_t* a, const uint32_t* b) {
    asm volatile(
        "mma.sync.aligned.m16n8k8.row.col.f32.tf32.tf32.f32 "
        "{%0,%1,%2,%3}, {%4,%5,%6,%7}, {%8,%9}, {%0,%1,%2,%3};"
        : "+f"(c[0]), "+f"(c[1]), "+f"(c[2]), "+f"(c[3])
        : "r"(a[0]), "r"(a[1]), "r"(a[2]), "r"(a[3]), "r"(b[0]), "r"(b[1]));
}

// smem tile row stride: 36 words (144 B) -> conflict-free fragment LDS
#define TS 36

// Shared memory pool (45 KB), word offsets:
//   phase 1: As1 @ 0        (64*36  = 2304 w)   [pair][d-chunk]
//            Bs1 @ 2304     (128*36 = 4608 w)   [h][d-chunk]
//   phase 2: As2 @ 0        (4*64*36 = 9216 w)  [h-chunk][pair][h-in-chunk]  (aliases As1/Bs1)
//            Bs2 @ 9216     (64*36  = 2304 w)   [d-row][h-in-chunk]          (no alias)
#define SM_WORDS 11520
#define BS1_OFF  2304
#define AS2_CH   2304
#define BS2_OFF  9216

// ---------------------------------------------------------------------------
// Kernel 0: zero the output AND bucket the 1024 (token,k) pairs by expert.
// ---------------------------------------------------------------------------
__global__ void init_kernel(const int* __restrict__ expert_indices,
                            float* __restrict__ out) {
    int tid = threadIdx.x;
    out[blockIdx.x * 1024 + tid] = 0.0f;     // 128*1024 == NT*ND exactly

    if (blockIdx.x == 0) {
        if (tid < NE) g_counts[tid] = 0;
        __syncthreads();
        int e = expert_indices[tid];         // pair id == flat [B,S,K] index
        int slot = atomicAdd(&g_counts[e], 1);
        g_pairs[e * NP + slot] = tid;
    }
}

// ---------------------------------------------------------------------------
// Fused kernel: for 64 pairs x 128 h-slice:
//   phase 1: hid = x . keys[e][hslice]  (TF32 MMA, K=D=256 in 8 chunks)
//   transition: gelu(hid) -> TF32 -> smem As2 (4 h-chunks of 32)
//   phase 2: out += w * As2 . values[e][:,hslice]^T
//            (16 steps: 4 d-subblocks x 4 h-chunks; atomic epilogue per dsub)
// Block 256 (8 warps). grid = (8 hslices, 16 mtiles, 16 experts).
// ---------------------------------------------------------------------------
__global__ __launch_bounds__(256) void fused_moe(const float* __restrict__ x,
                                                 const float* __restrict__ keys,
                                                 const float* __restrict__ values,
                                                 const float* __restrict__ expert_weights,
                                                 float* __restrict__ out) {
    const int e  = blockIdx.z;
    const int n  = g_counts[e];
    const int mt = blockIdx.y;
    if (mt * 64 >= n) return;
    const int hb = blockIdx.x * 128;

    __shared__ uint32_t SM[SM_WORDS];

    const int tid  = threadIdx.x;
    const int lane = tid & 31;
    const int w    = tid >> 5;
    const int qr   = lane >> 2;        // quad row 0..7
    const int qc   = lane & 3;         // quad col 0..3
    const int lrow = tid >> 3;         // 0..31
    const int lf4  = tid & 7;

    // ---- phase 1 warp grid: 2M x 4N over 64p x 128h ----
    const int wm = (w & 1) * 32;
    const int wn = (w >> 1) * 32;

    // A rows = gathered pairs (2/thread); B rows = h (4/thread)
    const float* ap[2];
    #pragma unroll
    for (int i = 0; i < 2; i++) {
        int pi = mt * 64 + lrow + 32 * i;
        int pr = (pi < n) ? g_pairs[e * NP + pi] : -1;
        ap[i] = (pr >= 0) ? (x + (size_t)(pr >> 1) * ND) : nullptr;
    }
    const float* kb = keys + (size_t)e * NH * ND + (size_t)hb * ND;

    float acc1[2][4][4];               // [mf][nf][c]
    #pragma unroll
    for (int mf = 0; mf < 2; mf++)
        #pragma unroll
        for (int nf = 0; nf < 4; nf++)
            #pragma unroll
            for (int j = 0; j < 4; j++) acc1[mf][nf][j] = 0.0f;

    float4 ar[2], br[4];
    #pragma unroll
    for (int i = 0; i < 2; i++)
        ar[i] = ap[i] ? *(const float4*)(ap[i] + lf4 * 4) : make_float4(0, 0, 0, 0);
    #pragma unroll
    for (int i = 0; i < 4; i++)
        br[i] = *(const float4*)(kb + (size_t)(lrow + 32 * i) * ND + lf4 * 4);
    #pragma unroll
    for (int i = 0; i < 2; i++)
        *(uint4*)&SM[(lrow + 32 * i) * TS + lf4 * 4] = to_tf32x4(ar[i]);
    #pragma unroll
    for (int i = 0; i < 4; i++)
        *(uint4*)&SM[BS1_OFF + (lrow + 32 * i) * TS + lf4 * 4] = to_tf32x4(br[i]);
    __syncthreads();

    for (int c = 0; c < 8; c++) {
        if (c < 7) {                   // prefetch next d-chunk
            int d0 = (c + 1) * 32;
            #pragma unroll
            for (int i = 0; i < 2; i++)
                ar[i] = ap[i] ? *(const float4*)(ap[i] + d0 + lf4 * 4)
                              : make_float4(0, 0, 0, 0);
            #pragma unroll
            for (int i = 0; i < 4; i++)
                br[i] = *(const float4*)(kb + (size_t)(lrow + 32 * i) * ND + d0 + lf4 * 4);
        }

        #pragma unroll
        for (int ks = 0; ks < 4; ks++) {
            const int k0 = ks * 8 + qc;
            uint32_t af[2][4], bf[4][2];
            #pragma unroll
            for (int mf = 0; mf < 2; mf++) {
                int r = wm + mf * 16 + qr;
                af[mf][0] = SM[r * TS + k0];           af[mf][1] = SM[(r + 8) * TS + k0];
                af[mf][2] = SM[r * TS + k0 + 4];       af[mf][3] = SM[(r + 8) * TS + k0 + 4];
            }
            #pragma unroll
            for (int nf = 0; nf < 4; nf++) {
                int cn = wn + nf * 8 + qr;
                bf[nf][0] = SM[BS1_OFF + cn * TS + k0];
                bf[nf][1] = SM[BS1_OFF + cn * TS + k0 + 4];
            }
            #pragma unroll
            for (int mf = 0; mf < 2; mf++)
                #pragma unroll
                for (int nf = 0; nf < 4; nf++)
                    mma_tf32(acc1[mf][nf], af[mf], bf[nf]);
        }

        if (c < 7) {
            __syncthreads();
            #pragma unroll
            for (int i = 0; i < 2; i++)
                *(uint4*)&SM[(lrow + 32 * i) * TS + lf4 * 4] = to_tf32x4(ar[i]);
            #pragma unroll
            for (int i = 0; i < 4; i++)
                *(uint4*)&SM[BS1_OFF + (lrow + 32 * i) * TS + lf4 * 4] = to_tf32x4(br[i]);
            __syncthreads();
        }
    }

    // ---- transition: prefetch first values tile, then gelu -> As2 ----
    const float* vb = values + (size_t)e * ND * NH + hb;  // [d][h] rows, this h-slice

    float4 vr[2];
    #pragma unroll
    for (int i = 0; i < 2; i++)   // step 0: dsub=0, hchunk=0
        vr[i] = *(const float4*)(vb + (size_t)(lrow + 32 * i) * NH + lf4 * 4);
    // Bs2 region does not alias phase-1 tiles: store now.
    #pragma unroll
    for (int i = 0; i < 2; i++)
        *(uint4*)&SM[BS2_OFF + (lrow + 32 * i) * TS + lf4 * 4] = to_tf32x4(vr[i]);

    __syncthreads();               // all phase-1 smem reads complete

    // gelu + TF32 into As2. Warp w owns h-chunk (w>>1); cols nf*8+2qc.
    {
        const int ch = w >> 1;
        #pragma unroll
        for (int mf = 0; mf < 2; mf++)
            #pragma unroll
            for (int half = 0; half < 2; half++) {
                int row = wm + mf * 16 + qr + half * 8;
                #pragma unroll
                for (int nf = 0; nf < 4; nf++) {
                    int col = nf * 8 + 2 * qc;
                    uint2 o;
                    o.x = to_tf32(gelu_tanh(acc1[mf][nf][half * 2 + 0]));
                    o.y = to_tf32(gelu_tanh(acc1[mf][nf][half * 2 + 1]));
                    *(uint2*)&SM[ch * AS2_CH + row * TS + col] = o;
                }
            }
    }

    // prefetch step 1 tile while As2 settles
    #pragma unroll
    for (int i = 0; i < 2; i++)
        vr[i] = *(const float4*)(vb + (size_t)(lrow + 32 * i) * NH + 32 + lf4 * 4);

    __syncthreads();               // As2 + Bs2(step0) visible

    // ---- phase 2: 16 steps (dsub = s>>2 selects 64 d-rows; hch = s&3) ----
    // warp grid 2M x 4N over 64p x 64d: wm2 rows, wn2 = (w>>1)*16 d-cols.
    const int wm2 = wm;
    const int wn2 = (w >> 1) * 16;

    // epilogue pair info
    float wgt[2][2];
    int   tok[2][2];
    #pragma unroll
    for (int mf = 0; mf < 2; mf++)
        #pragma unroll
        for (int half = 0; half < 2; half++) {
            int pi = mt * 64 + wm2 + mf * 16 + qr + half * 8;
            if (pi < n) {
                int pr = g_pairs[e * NP + pi];
                wgt[mf][half] = expert_weights[pr];
                tok[mf][half] = pr >> 1;
            } else {
                wgt[mf][half] = 0.0f;
                tok[mf][half] = -1;
            }
        }

    float acc2[2][2][4];
    #pragma unroll
    for (int mf = 0; mf < 2; mf++)
        #pragma unroll
        for (int nf = 0; nf < 2; nf++)
            #pragma unroll
            for (int j = 0; j < 4; j++) acc2[mf][nf][j] = 0.0f;

    for (int s = 0; s < 16; s++) {
        const int hch = s & 3;

        if (s < 15) {                  // prefetch step s+1 values tile
            int s1 = s + 1;
            const float* vp = vb + (size_t)((s1 >> 2) * 64) * NH + (s1 & 3) * 32;
            #pragma unroll
            for (int i = 0; i < 2; i++)
                vr[i] = *(const float4*)(vp + (size_t)(lrow + 32 * i) * NH + lf4 * 4);
        }

        #pragma unroll
        for (int ks = 0; ks < 4; ks++) {
            const int k0 = ks * 8 + qc;
            const uint32_t* A2 = &SM[hch * AS2_CH];
            uint32_t af[2][4], bf[2][2];
            #pragma unroll
            for (int mf = 0; mf < 2; mf++) {
                int r = wm2 + mf * 16 + qr;
                af[mf][0] = A2[r * TS + k0];       af[mf][1] = A2[(r + 8) * TS + k0];
                af[mf][2] = A2[r * TS + k0 + 4];   af[mf][3] = A2[(r + 8) * TS + k0 + 4];
            }
            #pragma unroll
            for (int nf = 0; nf < 2; nf++) {
                int cn = wn2 + nf * 8 + qr;
                bf[nf][0] = SM[BS2_OFF + cn * TS + k0];
                bf[nf][1] = SM[BS2_OFF + cn * TS + k0 + 4];
            }
            #pragma unroll
            for (int mf = 0; mf < 2; mf++)
                #pragma unroll
                for (int nf = 0; nf < 2; nf++)
                    mma_tf32(acc2[mf][nf], af[mf], bf[nf]);
        }

        if (hch == 3) {                // dsub complete: weighted atomic epilogue
            const int dbase = (s >> 2) * 64 + wn2;
            #pragma unroll
            for (int mf = 0; mf < 2; mf++)
                #pragma unroll
                for (int half = 0; half < 2; half++) {
                    if (tok[mf][half] >= 0) {
                        float* op = out + (size_t)tok[mf][half] * ND + dbase;
                        float g = wgt[mf][half];
                        #pragma unroll
                        for (int nf = 0; nf < 2; nf++) {
                            int col = nf * 8 + 2 * qc;
                            atomicAdd(op + col,     g * acc2[mf][nf][half * 2 + 0]);
                            atomicAdd(op + col + 1, g * acc2[mf][nf][half * 2 + 1]);
                        }
                    }
                }
            #pragma unroll
            for (int mf = 0; mf < 2; mf++)
                #pragma unroll
                for (int nf = 0; nf < 2; nf++)
                    #pragma unroll
                    for (int j = 0; j < 4; j++) acc2[mf][nf][j] = 0.0f;
        }

        if (s < 15) {
            __syncthreads();           // Bs2 reads done
            #pragma unroll
            for (int i = 0; i < 2; i++)
                *(uint4*)&SM[BS2_OFF + (lrow + 32 * i) * TS + lf4 * 4] = to_tf32x4(vr[i]);
            __syncthreads();           // Bs2 refilled
        }
    }
}

extern "C" void kernel_launch(void* const* d_in, const int* in_sizes, int n_in,
                              void* d_out, int out_size) {
    const float* x              = (const float*)d_in[0];
    const float* keys           = (const float*)d_in[1];
    const float* values         = (const float*)d_in[2];
    const float* expert_weights = (const float*)d_in[3];
    const int*   expert_indices = (const int*)d_in[4];
    float* out = (float*)d_out;

    init_kernel<<<NT * ND / 1024, 1024>>>(expert_indices, out);  // zero + bucket

    dim3 g(NH / 128, NP / 64, NE);      // (8, 16, 16); inactive mtiles exit
    fused_moe<<<g, 256>>>(x, keys, values, expert_weights, out);
}

// round 17
// speedup vs baseline: 1.4981x; 1.4981x over previous
#include <cuda_runtime.h>
#include <cuda_fp16.h>
#include <cstdint>

// Problem constants
#define NB 2
#define NS 256
#define ND 256
#define NH 1024
#define NE 16
#define NK 2

constexpr int NT = NB * NS;      // 512 tokens
constexpr int NP = NT * NK;      // 1024 (token, k) pairs

// Scratch (device globals: allocation-free per harness rules)
__device__ int   g_counts[NE];
__device__ int   g_pairs[NE * NP];
__device__ float g_hidden[(size_t)NP * NH];   // 4 MB

__device__ __forceinline__ float gelu_tanh(float v) {
    const float c = 0.7978845608028654f;  // sqrt(2/pi)
    float u = c * (v + 0.044715f * v * v * v);
    return 0.5f * v * (1.0f + tanhf(u));
}

// float4 -> 2x half2 (round-to-nearest; fp16 mantissa == tf32 mantissa)
__device__ __forceinline__ uint2 f4_to_h2x2(float4 v) {
    __half2 a = __floats2half2_rn(v.x, v.y);
    __half2 b = __floats2half2_rn(v.z, v.w);
    uint2 r;
    r.x = *(uint32_t*)&a;
    r.y = *(uint32_t*)&b;
    return r;
}

// D(16x8) += A(16x16,row) * B(16x8,col), f16 inputs, f32 accum. sm_80+.
__device__ __forceinline__ void mma_f16(float* c, const uint32_t* a, const uint32_t* b) {
    asm volatile(
        "mma.sync.aligned.m16n8k16.row.col.f32.f16.f16.f32 "
        "{%0,%1,%2,%3}, {%4,%5,%6,%7}, {%8,%9}, {%0,%1,%2,%3};"
        : "+f"(c[0]), "+f"(c[1]), "+f"(c[2]), "+f"(c[3])
        : "r"(a[0]), "r"(a[1]), "r"(a[2]), "r"(a[3]), "r"(b[0]), "r"(b[1]));
}

// smem tile row stride: 36 words (32 half2-words of data = K=64 halfs + pad)
// -> fragment LDS addr (4r + k0) % 32 spans 32 distinct banks.
#define TS 36

// ---------------------------------------------------------------------------
// Kernel 0: zero the output AND bucket the 1024 (token,k) pairs by expert.
// ---------------------------------------------------------------------------
__global__ void init_kernel(const int* __restrict__ expert_indices,
                            float* __restrict__ out) {
    int tid = threadIdx.x;
    out[blockIdx.x * 1024 + tid] = 0.0f;     // 128*1024 == NT*ND exactly

    if (blockIdx.x == 0) {
        if (tid < NE) g_counts[tid] = 0;
        __syncthreads();
        int e = expert_indices[tid];         // pair id == flat [B,S,K] index
        int slot = atomicAdd(&g_counts[e], 1);
        g_pairs[e * NP + slot] = tid;
    }
}

// ---------------------------------------------------------------------------
// Kernel 1 (mma.sync FP16): hidden[pair, h] = gelu( x[token] . keys[e][h] )
// CTA: 64 pairs x 128 h, K=D=256 in 4 chunks of 64 halfs. Block 256 (8 warps,
// warp grid 2M x 4N, warp tile 32x32 -> 2 mf x 4 nf, k16 steps).
// grid = (NH/128, 16 mtiles, NE); inactive mtiles exit.
// ---------------------------------------------------------------------------
__global__ __launch_bounds__(256, 2) void ffn1_mma(const float* __restrict__ x,
                                                   const float* __restrict__ keys) {
    const int e  = blockIdx.z;
    const int n  = g_counts[e];
    const int mt = blockIdx.y;
    if (mt * 64 >= n) return;
    const int hb = blockIdx.x * 128;

    __shared__ uint32_t As[64][TS];    // [pair][d-halfs as half2 words]
    __shared__ uint32_t Bs[128][TS];   // [h][d-halfs]

    const int tid  = threadIdx.x;
    const int lane = tid & 31;
    const int w    = tid >> 5;
    const int wm   = (w & 1) * 32;     // warp M offset
    const int wn   = (w >> 1) * 32;    // warp N offset
    const int qr   = lane >> 2;        // quad row 0..7
    const int qc   = lane & 3;         // quad col 0..3

    const int lrow = tid >> 3;         // 0..31
    const int lf4  = tid & 7;          // float4 col within first 32 floats

    const float* ap[2];
    #pragma unroll
    for (int i = 0; i < 2; i++) {
        int pi = mt * 64 + lrow + 32 * i;
        int pr = (pi < n) ? g_pairs[e * NP + pi] : -1;
        ap[i] = (pr >= 0) ? (x + (size_t)(pr >> 1) * ND) : nullptr;
    }
    const float* kb = keys + (size_t)e * NH * ND + (size_t)hb * ND;

    float acc[2][4][4];                // [mf][nf][c0..c3]
    #pragma unroll
    for (int mf = 0; mf < 2; mf++)
        #pragma unroll
        for (int nf = 0; nf < 4; nf++)
            #pragma unroll
            for (int j = 0; j < 4; j++) acc[mf][nf][j] = 0.0f;

    // chunk = 64 floats: per thread A 2 rows x 2 f4 (cols lf4, lf4+8); B 4 rows x 2 f4
    float4 ar[2][2], br[4][2];
    #pragma unroll
    for (int i = 0; i < 2; i++) {
        ar[i][0] = ap[i] ? *(const float4*)(ap[i] + lf4 * 4)        : make_float4(0, 0, 0, 0);
        ar[i][1] = ap[i] ? *(const float4*)(ap[i] + (lf4 + 8) * 4)  : make_float4(0, 0, 0, 0);
    }
    #pragma unroll
    for (int i = 0; i < 4; i++) {
        const float* kr = kb + (size_t)(lrow + 32 * i) * ND;
        br[i][0] = *(const float4*)(kr + lf4 * 4);
        br[i][1] = *(const float4*)(kr + (lf4 + 8) * 4);
    }
    #pragma unroll
    for (int i = 0; i < 2; i++) {
        *(uint2*)&As[lrow + 32 * i][lf4 * 2]      = f4_to_h2x2(ar[i][0]);
        *(uint2*)&As[lrow + 32 * i][lf4 * 2 + 16] = f4_to_h2x2(ar[i][1]);
    }
    #pragma unroll
    for (int i = 0; i < 4; i++) {
        *(uint2*)&Bs[lrow + 32 * i][lf4 * 2]      = f4_to_h2x2(br[i][0]);
        *(uint2*)&Bs[lrow + 32 * i][lf4 * 2 + 16] = f4_to_h2x2(br[i][1]);
    }
    __syncthreads();

    for (int c = 0; c < 4; c++) {
        if (c < 3) {                   // prefetch next 64-float chunk
            int d0 = (c + 1) * 64;
            #pragma unroll
            for (int i = 0; i < 2; i++) {
                ar[i][0] = ap[i] ? *(const float4*)(ap[i] + d0 + lf4 * 4)       : make_float4(0, 0, 0, 0);
                ar[i][1] = ap[i] ? *(const float4*)(ap[i] + d0 + (lf4 + 8) * 4) : make_float4(0, 0, 0, 0);
            }
            #pragma unroll
            for (int i = 0; i < 4; i++) {
                const float* kr = kb + (size_t)(lrow + 32 * i) * ND + d0;
                br[i][0] = *(const float4*)(kr + lf4 * 4);
                br[i][1] = *(const float4*)(kr + (lf4 + 8) * 4);
            }
        }

        #pragma unroll
        for (int ks = 0; ks < 4; ks++) {           // each ks = K of 16 halfs
            const int k0 = ks * 8 + qc;
            uint32_t af[2][4], bf[4][2];
            #pragma unroll
            for (int mf = 0; mf < 2; mf++) {
                int r = wm + mf * 16 + qr;
                af[mf][0] = As[r][k0];     af[mf][1] = As[r + 8][k0];
                af[mf][2] = As[r][k0 + 4]; af[mf][3] = As[r + 8][k0 + 4];
            }
            #pragma unroll
            for (int nf = 0; nf < 4; nf++) {
                int cn = wn + nf * 8 + qr;
                bf[nf][0] = Bs[cn][k0];
                bf[nf][1] = Bs[cn][k0 + 4];
            }
            #pragma unroll
            for (int mf = 0; mf < 2; mf++)
                #pragma unroll
                for (int nf = 0; nf < 4; nf++)
                    mma_f16(acc[mf][nf], af[mf], bf[nf]);
        }

        if (c < 3) {
            __syncthreads();
            #pragma unroll
            for (int i = 0; i < 2; i++) {
                *(uint2*)&As[lrow + 32 * i][lf4 * 2]      = f4_to_h2x2(ar[i][0]);
                *(uint2*)&As[lrow + 32 * i][lf4 * 2 + 16] = f4_to_h2x2(ar[i][1]);
            }
            #pragma unroll
            for (int i = 0; i < 4; i++) {
                *(uint2*)&Bs[lrow + 32 * i][lf4 * 2]      = f4_to_h2x2(br[i][0]);
                *(uint2*)&Bs[lrow + 32 * i][lf4 * 2 + 16] = f4_to_h2x2(br[i][1]);
            }
            __syncthreads();
        }
    }

    // Epilogue: gelu + float2 stores (c0,c1 adjacent cols 2qc,2qc+1)
    #pragma unroll
    for (int mf = 0; mf < 2; mf++) {
        #pragma unroll
        for (int half = 0; half < 2; half++) {
            int row = wm + mf * 16 + qr + half * 8;
            int pi  = mt * 64 + row;
            if (pi < n) {
                int pr = g_pairs[e * NP + pi];
                float* hp = g_hidden + (size_t)pr * NH + hb;
                #pragma unroll
                for (int nf = 0; nf < 4; nf++) {
                    int col = wn + nf * 8 + 2 * qc;
                    float2 o;
                    o.x = gelu_tanh(acc[mf][nf][half * 2 + 0]);
                    o.y = gelu_tanh(acc[mf][nf][half * 2 + 1]);
                    *(float2*)(hp + col) = o;
                }
            }
        }
    }
}

// ---------------------------------------------------------------------------
// Kernel 2 (mma.sync FP16): out[token,d] += w * sum_h hidden[pair,h]*values[e][d][h]
// CTA: 64 pairs x 128 d, K = 256 h (its hsplit of 4) in 4 chunks of 64.
// grid = (2 dtile * 4 hsplit, 16 mtiles, NE), block 256.
// ---------------------------------------------------------------------------
__global__ __launch_bounds__(256, 2) void ffn2_mma(const float* __restrict__ values,
                                                   const float* __restrict__ expert_weights,
                                                   float* __restrict__ out) {
    const int e  = blockIdx.z;
    const int n  = g_counts[e];
    const int mt = blockIdx.y;
    if (mt * 64 >= n) return;
    const int db    = (blockIdx.x & 1) * 128;
    const int hbase = (blockIdx.x >> 1) * 256;

    __shared__ uint32_t As[64][TS];    // [pair][h-halfs]
    __shared__ uint32_t Bs[128][TS];   // [d][h-halfs]

    const int tid  = threadIdx.x;
    const int lane = tid & 31;
    const int w    = tid >> 5;
    const int wm   = (w & 1) * 32;
    const int wn   = (w >> 1) * 32;
    const int qr   = lane >> 2;
    const int qc   = lane & 3;

    const int lrow = tid >> 3;
    const int lf4  = tid & 7;

    const float* ap[2];
    #pragma unroll
    for (int i = 0; i < 2; i++) {
        int pi = mt * 64 + lrow + 32 * i;
        int pr = (pi < n) ? g_pairs[e * NP + pi] : -1;
        ap[i] = (pr >= 0) ? (g_hidden + (size_t)pr * NH + hbase) : nullptr;
    }
    const float* vb = values + (size_t)e * ND * NH + (size_t)db * NH + hbase;

    float acc[2][4][4];
    #pragma unroll
    for (int mf = 0; mf < 2; mf++)
        #pragma unroll
        for (int nf = 0; nf < 4; nf++)
            #pragma unroll
            for (int j = 0; j < 4; j++) acc[mf][nf][j] = 0.0f;

    float4 ar[2][2], br[4][2];
    #pragma unroll
    for (int i = 0; i < 2; i++) {
        ar[i][0] = ap[i] ? *(const float4*)(ap[i] + lf4 * 4)       : make_float4(0, 0, 0, 0);
        ar[i][1] = ap[i] ? *(const float4*)(ap[i] + (lf4 + 8) * 4) : make_float4(0, 0, 0, 0);
    }
    #pragma unroll
    for (int i = 0; i < 4; i++) {
        const float* vr = vb + (size_t)(lrow + 32 * i) * NH;
        br[i][0] = *(const float4*)(vr + lf4 * 4);
        br[i][1] = *(const float4*)(vr + (lf4 + 8) * 4);
    }
    #pragma unroll
    for (int i = 0; i < 2; i++) {
        *(uint2*)&As[lrow + 32 * i][lf4 * 2]      = f4_to_h2x2(ar[i][0]);
        *(uint2*)&As[lrow + 32 * i][lf4 * 2 + 16] = f4_to_h2x2(ar[i][1]);
    }
    #pragma unroll
    for (int i = 0; i < 4; i++) {
        *(uint2*)&Bs[lrow + 32 * i][lf4 * 2]      = f4_to_h2x2(br[i][0]);
        *(uint2*)&Bs[lrow + 32 * i][lf4 * 2 + 16] = f4_to_h2x2(br[i][1]);
    }
    __syncthreads();

    for (int c = 0; c < 4; c++) {
        if (c < 3) {
            int h0 = (c + 1) * 64;
            #pragma unroll
            for (int i = 0; i < 2; i++) {
                ar[i][0] = ap[i] ? *(const float4*)(ap[i] + h0 + lf4 * 4)       : make_float4(0, 0, 0, 0);
                ar[i][1] = ap[i] ? *(const float4*)(ap[i] + h0 + (lf4 + 8) * 4) : make_float4(0, 0, 0, 0);
            }
            #pragma unroll
            for (int i = 0; i < 4; i++) {
                const float* vr = vb + (size_t)(lrow + 32 * i) * NH + h0;
                br[i][0] = *(const float4*)(vr + lf4 * 4);
                br[i][1] = *(const float4*)(vr + (lf4 + 8) * 4);
            }
        }

        #pragma unroll
        for (int ks = 0; ks < 4; ks++) {
            const int k0 = ks * 8 + qc;
            uint32_t af[2][4], bf[4][2];
            #pragma unroll
            for (int mf = 0; mf < 2; mf++) {
                int r = wm + mf * 16 + qr;
                af[mf][0] = As[r][k0];     af[mf][1] = As[r + 8][k0];
                af[mf][2] = As[r][k0 + 4]; af[mf][3] = As[r + 8][k0 + 4];
            }
            #pragma unroll
            for (int nf = 0; nf < 4; nf++) {
                int cn = wn + nf * 8 + qr;
                bf[nf][0] = Bs[cn][k0];
                bf[nf][1] = Bs[cn][k0 + 4];
            }
            #pragma unroll
            for (int mf = 0; mf < 2; mf++)
                #pragma unroll
                for (int nf = 0; nf < 4; nf++)
                    mma_f16(acc[mf][nf], af[mf], bf[nf]);
        }

        if (c < 3) {
            __syncthreads();
            #pragma unroll
            for (int i = 0; i < 2; i++) {
                *(uint2*)&As[lrow + 32 * i][lf4 * 2]      = f4_to_h2x2(ar[i][0]);
                *(uint2*)&As[lrow + 32 * i][lf4 * 2 + 16] = f4_to_h2x2(ar[i][1]);
            }
            #pragma unroll
            for (int i = 0; i < 4; i++) {
                *(uint2*)&Bs[lrow + 32 * i][lf4 * 2]      = f4_to_h2x2(br[i][0]);
                *(uint2*)&Bs[lrow + 32 * i][lf4 * 2 + 16] = f4_to_h2x2(br[i][1]);
            }
            __syncthreads();
        }
    }

    // Epilogue: weighted atomic accumulation into out
    #pragma unroll
    for (int mf = 0; mf < 2; mf++) {
        #pragma unroll
        for (int half = 0; half < 2; half++) {
            int row = wm + mf * 16 + qr + half * 8;
            int pi  = mt * 64 + row;
            if (pi < n) {
                int pr = g_pairs[e * NP + pi];
                float wgt = expert_weights[pr];       // flat [B,S,K] index == pair id
                float* op = out + (size_t)(pr >> 1) * ND + db;
                #pragma unroll
                for (int nf = 0; nf < 4; nf++) {
                    int col = wn + nf * 8 + 2 * qc;
                    atomicAdd(op + col,     wgt * acc[mf][nf][half * 2 + 0]);
                    atomicAdd(op + col + 1, wgt * acc[mf][nf][half * 2 + 1]);
                }
            }
        }
    }
}

extern "C" void kernel_launch(void* const* d_in, const int* in_sizes, int n_in,
                              void* d_out, int out_size) {
    const float* x              = (const float*)d_in[0];
    const float* keys           = (const float*)d_in[1];
    const float* values         = (const float*)d_in[2];
    const float* expert_weights = (const float*)d_in[3];
    const int*   expert_indices = (const int*)d_in[4];
    float* out = (float*)d_out;

    init_kernel<<<NT * ND / 1024, 1024>>>(expert_indices, out);  // zero + bucket

    dim3 g1(NH / 128, NP / 64, NE);     // (8, 16, 16); inactive mtiles exit
    ffn1_mma<<<g1, 256>>>(x, keys);

    dim3 g2(2 * 4, NP / 64, NE);        // (8, 16, 16)
    ffn2_mma<<<g2, 256>>>(values, expert_weights, out);
}